// round 3
// baseline (speedup 1.0000x reference)
#include <cuda_runtime.h>
#include <cuda_fp16.h>

#define N_NODES   50000
#define N_PAIRS   800000
#define TILE_M    128
#define N_TILES   (N_PAIRS / TILE_M)       // 6250

// ---------------- main-kernel SMEM layout ----------------
#define PITCH     528                       // 264 halves per row (256 + 8 pad)
#define SM_AHI    0
#define SM_ALO    67584                     // 128*528
#define SM_B      135168
#define SM_BUF    33792                     // 64*528
#define SM_SIZE   202752                    // 135168 + 2*33792

// ---------------- device scratch ----------------
__device__ __align__(16) float  g_q[(size_t)N_NODES * 256];   // p1 @ W1, fp32
__device__ __align__(16) __half g_w2t[512 * 256];             // W2^T as [n][k] fp16

// ---------------- helpers ----------------
__device__ __forceinline__ unsigned smem_u32(const void* p) {
    unsigned a;
    asm("{ .reg .u64 t; cvta.to.shared.u64 t, %1; cvt.u32.u64 %0, t; }" : "=r"(a) : "l"(p));
    return a;
}

__device__ __forceinline__ void ldmx4(unsigned* r, unsigned addr) {
    asm volatile("ldmatrix.sync.aligned.m8n8.x4.shared.b16 {%0,%1,%2,%3}, [%4];"
                 : "=r"(r[0]), "=r"(r[1]), "=r"(r[2]), "=r"(r[3]) : "r"(addr));
}

__device__ __forceinline__ void mma16816(float* c, const unsigned* a, unsigned b0, unsigned b1) {
    asm volatile("mma.sync.aligned.m16n8k16.row.col.f32.f16.f16.f32 "
                 "{%0,%1,%2,%3}, {%4,%5,%6,%7}, {%8,%9}, {%0,%1,%2,%3};"
                 : "+f"(c[0]), "+f"(c[1]), "+f"(c[2]), "+f"(c[3])
                 : "r"(a[0]), "r"(a[1]), "r"(a[2]), "r"(a[3]), "r"(b0), "r"(b1));
}

#define CP16(sm, g)  asm volatile("cp.async.cg.shared.global [%0], [%1], 16;" :: "r"(sm), "l"(g) : "memory")
#define CP_COMMIT()  asm volatile("cp.async.commit_group;" ::: "memory")
#define CP_WAIT(n)   asm volatile("cp.async.wait_group %0;" :: "n"(n) : "memory")

// FMA-only tanh: ~1e-7 relative accuracy, zero MUFU.
__device__ __forceinline__ float fast_tanh(float x) {
    float y = x * 2.885390081777927f;                 // 2x * log2(e)
    y = fminf(fmaxf(y, -30.0f), 30.0f);
    float t  = y + 12582912.0f;                       // round-to-nearest int
    float nf = t - 12582912.0f;
    float f  = y - nf;
    float p  = 1.5403530e-4f;
    p = fmaf(p, f, 1.3333558e-3f);
    p = fmaf(p, f, 9.6181291e-3f);
    p = fmaf(p, f, 5.5504109e-2f);
    p = fmaf(p, f, 2.4022651e-1f);
    p = fmaf(p, f, 6.9314718e-1f);
    p = fmaf(p, f, 1.0f);                             // 2^f
    float s  = __int_as_float(((int)nf + 127) << 23); // 2^n
    float ex = p * s;                                 // e^{2x}
    float den = ex + 1.0f;
    float r = __int_as_float(0x7EF311C3 - __float_as_int(den));
    r = r * (2.0f - den * r);
    r = r * (2.0f - den * r);
    r = r * (2.0f - den * r);                         // 1/(e^{2x}+1)
    return fmaf(-2.0f, r, 1.0f);
}

// ---------------- kernel A: q = p1 @ W1 (fp32) ----------------
__global__ __launch_bounds__(256) void pil_q(const float* __restrict__ p1,
                                             const float* __restrict__ W1,
                                             float* __restrict__ q) {
    __shared__ float sA[64 * 68];
    __shared__ float sB[64 * 68];
    int tid = threadIdx.x;
    int m0 = blockIdx.x * 64, n0 = blockIdx.y * 64;

    #pragma unroll
    for (int i = 0; i < 4; i++) {
        int v = tid + i * 256;
        int r = v >> 4, c4 = (v & 15) * 4;
        float4 av = make_float4(0.f, 0.f, 0.f, 0.f);
        if (m0 + r < N_NODES) av = *(const float4*)(p1 + (long)(m0 + r) * 64 + c4);
        *(float4*)(sA + r * 68 + c4) = av;
        *(float4*)(sB + r * 68 + c4) = *(const float4*)(W1 + (long)r * 256 + n0 + c4);
    }
    __syncthreads();

    int tx = tid & 15, ty = tid >> 4;
    float c[4][4];
    #pragma unroll
    for (int i = 0; i < 4; i++)
        #pragma unroll
        for (int j = 0; j < 4; j++) c[i][j] = 0.f;

    #pragma unroll 8
    for (int k = 0; k < 64; k++) {
        float4 b = *(float4*)(sB + k * 68 + tx * 4);
        #pragma unroll
        for (int i = 0; i < 4; i++) {
            float a = sA[(ty * 4 + i) * 68 + k];
            c[i][0] = fmaf(a, b.x, c[i][0]);
            c[i][1] = fmaf(a, b.y, c[i][1]);
            c[i][2] = fmaf(a, b.z, c[i][2]);
            c[i][3] = fmaf(a, b.w, c[i][3]);
        }
    }
    #pragma unroll
    for (int i = 0; i < 4; i++) {
        int m = m0 + ty * 4 + i;
        if (m < N_NODES) {
            float4 o; o.x = c[i][0]; o.y = c[i][1]; o.z = c[i][2]; o.w = c[i][3];
            *(float4*)(q + (long)m * 256 + n0 + tx * 4) = o;
        }
    }
}

// ---------------- prep: W2^T fp16 ----------------
__global__ __launch_bounds__(256) void pil_prep(const float* __restrict__ W2) {
    int t = blockIdx.x * 256 + threadIdx.x;   // 0..131071 ; t = k*512 + n
    int k = t >> 9, n = t & 511;
    g_w2t[n * 256 + k] = __float2half_rn(W2[t]);
}

// ---------------- main: gather + tanh + GEMM2 + basis einsum ----------------
__global__ __launch_bounds__(256, 1) void pil_main(const void* __restrict__ pi,
                                                   const void* __restrict__ pj,
                                                   const float* __restrict__ basis,
                                                   float* __restrict__ out) {
    extern __shared__ char smem[];
    unsigned sb = smem_u32(smem);
    int tid  = threadIdx.x;
    int w    = tid >> 5;
    int l    = tid & 31;
    long pairbase = (long)blockIdx.x * TILE_M;

    // -- start W2 chunk 0/1 copies immediately (overlap with gather) --
    {
        #pragma unroll
        for (int i = 0; i < 8; i++) {
            int v = tid + i * 256;                    // 0..2047
            int r = v >> 5, seg = (v & 31) * 16;
            CP16(sb + SM_B + r * PITCH + seg, (const char*)g_w2t + (long)r * 512 + seg);
        }
        CP_COMMIT();
        #pragma unroll
        for (int i = 0; i < 8; i++) {
            int v = tid + i * 256;
            int r = v >> 5, seg = (v & 31) * 16;
            CP16(sb + SM_B + SM_BUF + r * PITCH + seg,
                 (const char*)g_w2t + (long)(64 + r) * 512 + seg);
        }
        CP_COMMIT();
    }

    // -- index dtype sniff (int64 vs silently-int32) --
    bool is64;
    {
        const unsigned* wds = (const unsigned*)pi;
        unsigned acc = 0;
        #pragma unroll
        for (int u = 1; u < 32; u += 2) acc |= wds[u];
        is64 = (acc == 0);
    }

    // -- basis fragments for epilogue --
    int r0 = 16 * w + (l >> 2);
    int s  = l & 3;
    float2 basA = *(const float2*)(basis + (pairbase + r0) * 8 + 2 * s);
    float2 basB = *(const float2*)(basis + (pairbase + r0 + 8) * 8 + 2 * s);

    // -- phase 1: gather q rows, tanh, fp16 hi/lo split -> SMEM A --
    {
        int row = tid >> 1, half = tid & 1;
        long p = pairbase + row;
        long ii, jj;
        if (is64) { ii = ((const long long*)pi)[p]; jj = ((const long long*)pj)[p]; }
        else      { ii = ((const int*)pi)[p];       jj = ((const int*)pj)[p]; }
        const float4* qi = (const float4*)(g_q + ii * 256 + half * 128);
        const float4* qj = (const float4*)(g_q + jj * 256 + half * 128);
        char* dst = smem + row * PITCH + half * 256;
        #pragma unroll 4
        for (int j = 0; j < 32; j++) {
            float4 a = qi[j], b = qj[j];
            float v0 = fast_tanh(a.x + b.x);
            float v1 = fast_tanh(a.y + b.y);
            float v2 = fast_tanh(a.z + b.z);
            float v3 = fast_tanh(a.w + b.w);
            __half h0 = __float2half_rn(v0), h1 = __float2half_rn(v1);
            __half h2 = __float2half_rn(v2), h3 = __float2half_rn(v3);
            __half e0 = __float2half_rn(v0 - __half2float(h0));
            __half e1 = __float2half_rn(v1 - __half2float(h1));
            __half e2 = __float2half_rn(v2 - __half2float(h2));
            __half e3 = __float2half_rn(v3 - __half2float(h3));
            uint2 hv, lv;
            hv.x = (unsigned)__half_as_ushort(h0) | ((unsigned)__half_as_ushort(h1) << 16);
            hv.y = (unsigned)__half_as_ushort(h2) | ((unsigned)__half_as_ushort(h3) << 16);
            lv.x = (unsigned)__half_as_ushort(e0) | ((unsigned)__half_as_ushort(e1) << 16);
            lv.y = (unsigned)__half_as_ushort(e2) | ((unsigned)__half_as_ushort(e3) << 16);
            *(uint2*)(dst + SM_AHI + j * 8) = hv;
            *(uint2*)(dst + SM_ALO + j * 8) = lv;
        }
    }

    // -- per-lane ldmatrix bases --
    unsigned rowA = 16 * w + (l & 7) + ((l >> 3) & 1) * 8;
    unsigned colA = (l >> 4) * 16;                          // bytes
    unsigned aHiBase = sb + SM_AHI + rowA * PITCH + colA;
    unsigned aLoBase = sb + SM_ALO + rowA * PITCH + colA;
    unsigned rowBl = (l & 7) + (l >> 4) * 8;
    unsigned colBl = ((l >> 3) & 1) * 16;
    unsigned bLane = rowBl * PITCH + colBl;

    // -- phase 2: 8 N-chunks of 64, double-buffered --
    for (int c = 0; c < 8; c++) {
        if (c < 7) CP_WAIT(1); else CP_WAIT(0);
        __syncthreads();                                    // chunk c resident, A ready

        unsigned bBase = sb + SM_B + (c & 1) * SM_BUF + bLane;
        float acc[8][4];
        #pragma unroll
        for (int n = 0; n < 8; n++)
            #pragma unroll
            for (int j = 0; j < 4; j++) acc[n][j] = 0.f;

        #pragma unroll
        for (int ks = 0; ks < 16; ks++) {
            unsigned ah[4], al[4], bb[4];
            ldmx4(ah, aHiBase + ks * 32);
            ldmx4(al, aLoBase + ks * 32);
            #pragma unroll
            for (int ntp = 0; ntp < 4; ntp++) {
                ldmx4(bb, bBase + ntp * (16 * PITCH) + ks * 32);
                mma16816(acc[2 * ntp],     ah, bb[0], bb[1]);
                mma16816(acc[2 * ntp],     al, bb[0], bb[1]);
                mma16816(acc[2 * ntp + 1], ah, bb[2], bb[3]);
                mma16816(acc[2 * ntp + 1], al, bb[2], bb[3]);
            }
        }
        __syncthreads();                                    // all reads of buf done
        if (c + 2 < 8) {                                    // refill buf (c&1) with chunk c+2
            unsigned dst = sb + SM_B + (c & 1) * SM_BUF;
            const char* src = (const char*)g_w2t + (long)(c + 2) * 64 * 512;
            #pragma unroll
            for (int i = 0; i < 8; i++) {
                int v = tid + i * 256;
                int r = v >> 5, seg = (v & 31) * 16;
                CP16(dst + r * PITCH + seg, src + (long)r * 512 + seg);
            }
            CP_COMMIT();
        }

        // epilogue: fold basis, reduce across the 4 lanes of each row-group, store
        #pragma unroll
        for (int nt = 0; nt < 8; nt++) {
            float v0 = acc[nt][0] * basA.x + acc[nt][1] * basA.y;
            float v1 = acc[nt][2] * basB.x + acc[nt][3] * basB.y;
            v0 += __shfl_xor_sync(0xFFFFFFFFu, v0, 1);
            v0 += __shfl_xor_sync(0xFFFFFFFFu, v0, 2);
            v1 += __shfl_xor_sync(0xFFFFFFFFu, v1, 1);
            v1 += __shfl_xor_sync(0xFFFFFFFFu, v1, 2);
            if ((l & 3) == 0) {
                int c_out = c * 8 + nt;
                out[(pairbase + r0) * 64 + c_out]     = v0;
                out[(pairbase + r0 + 8) * 64 + c_out] = v1;
            }
        }
    }
}

extern "C" void kernel_launch(void* const* d_in, const int* in_sizes, int n_in,
                              void* d_out, int out_size) {
    const float* p1    = (const float*)d_in[0];
    const void*  pi    = d_in[1];
    const void*  pj    = d_in[2];
    const float* basis = (const float*)d_in[3];
    const float* W1    = (const float*)d_in[4];
    const float* W2    = (const float*)d_in[5];
    (void)in_sizes; (void)n_in; (void)out_size;

    float* q;
    cudaGetSymbolAddress((void**)&q, g_q);

    cudaFuncSetAttribute(pil_main, cudaFuncAttributeMaxDynamicSharedMemorySize, SM_SIZE);

    pil_prep<<<512, 256>>>(W2);
    pil_q<<<dim3((N_NODES + 63) / 64, 4), 256>>>(p1, W1, q);
    pil_main<<<N_TILES, 256, SM_SIZE>>>(pi, pj, basis, (float*)d_out);
}

// round 6
// speedup vs baseline: 1.1662x; 1.1662x over previous
#include <cuda_runtime.h>
#include <cuda_fp16.h>

#define N_NODES   50000
#define N_PAIRS   800000
#define TILE_M    128
#define N_TILES   (N_PAIRS / TILE_M)       // 6250

// ---------------- main-kernel SMEM layout ----------------
#define PITCH     528                       // 264 halves per row (256 + 8 pad)
#define SM_A      0                         // 128*528 = 67584 (fp16 activations)
#define SM_B      67584                     // two 32-row chunks
#define SM_BUF    16896                     // 32*528
#define SM_SIZE   101376                    // 67584 + 2*16896  (x2 CTAs = 202752)

// ---------------- device scratch ----------------
__device__ __align__(16) float  g_q[(size_t)N_NODES * 256];   // p1 @ W1, fp32
__device__ __align__(16) __half g_w2t[512 * 256];             // W2^T as [n][k] fp16

// ---------------- helpers ----------------
__device__ __forceinline__ unsigned smem_u32(const void* p) {
    unsigned a;
    asm("{ .reg .u64 t; cvta.to.shared.u64 t, %1; cvt.u32.u64 %0, t; }" : "=r"(a) : "l"(p));
    return a;
}

__device__ __forceinline__ void ldmx4(unsigned* r, unsigned addr) {
    asm volatile("ldmatrix.sync.aligned.m8n8.x4.shared.b16 {%0,%1,%2,%3}, [%4];"
                 : "=r"(r[0]), "=r"(r[1]), "=r"(r[2]), "=r"(r[3]) : "r"(addr));
}

__device__ __forceinline__ void mma16816(float* c, const unsigned* a, unsigned b0, unsigned b1) {
    asm volatile("mma.sync.aligned.m16n8k16.row.col.f32.f16.f16.f32 "
                 "{%0,%1,%2,%3}, {%4,%5,%6,%7}, {%8,%9}, {%0,%1,%2,%3};"
                 : "+f"(c[0]), "+f"(c[1]), "+f"(c[2]), "+f"(c[3])
                 : "r"(a[0]), "r"(a[1]), "r"(a[2]), "r"(a[3]), "r"(b0), "r"(b1));
}

__device__ __forceinline__ float tanh_approx(float x) {
    float r;
    asm("tanh.approx.f32 %0, %1;" : "=f"(r) : "f"(x));
    return r;
}

#define CP16(sm, g)  asm volatile("cp.async.cg.shared.global [%0], [%1], 16;" :: "r"(sm), "l"(g) : "memory")
#define CP_COMMIT()  asm volatile("cp.async.commit_group;" ::: "memory")
#define CP_WAIT(n)   asm volatile("cp.async.wait_group %0;" :: "n"(n) : "memory")

// ---------------- kernel A: q = p1 @ W1 (fp32) ----------------
__global__ __launch_bounds__(256) void pil_q(const float* __restrict__ p1,
                                             const float* __restrict__ W1,
                                             float* __restrict__ q) {
    __shared__ float sA[64 * 68];
    __shared__ float sB[64 * 68];
    int tid = threadIdx.x;
    int m0 = blockIdx.x * 64, n0 = blockIdx.y * 64;

    #pragma unroll
    for (int i = 0; i < 4; i++) {
        int v = tid + i * 256;
        int r = v >> 4, c4 = (v & 15) * 4;
        float4 av = make_float4(0.f, 0.f, 0.f, 0.f);
        if (m0 + r < N_NODES) av = *(const float4*)(p1 + (long)(m0 + r) * 64 + c4);
        *(float4*)(sA + r * 68 + c4) = av;
        *(float4*)(sB + r * 68 + c4) = *(const float4*)(W1 + (long)r * 256 + n0 + c4);
    }
    __syncthreads();

    int tx = tid & 15, ty = tid >> 4;
    float c[4][4];
    #pragma unroll
    for (int i = 0; i < 4; i++)
        #pragma unroll
        for (int j = 0; j < 4; j++) c[i][j] = 0.f;

    #pragma unroll 8
    for (int k = 0; k < 64; k++) {
        float4 b = *(float4*)(sB + k * 68 + tx * 4);
        #pragma unroll
        for (int i = 0; i < 4; i++) {
            float a = sA[(ty * 4 + i) * 68 + k];
            c[i][0] = fmaf(a, b.x, c[i][0]);
            c[i][1] = fmaf(a, b.y, c[i][1]);
            c[i][2] = fmaf(a, b.z, c[i][2]);
            c[i][3] = fmaf(a, b.w, c[i][3]);
        }
    }
    #pragma unroll
    for (int i = 0; i < 4; i++) {
        int m = m0 + ty * 4 + i;
        if (m < N_NODES) {
            float4 o; o.x = c[i][0]; o.y = c[i][1]; o.z = c[i][2]; o.w = c[i][3];
            *(float4*)(q + (long)m * 256 + n0 + tx * 4) = o;
        }
    }
}

// ---------------- prep: W2^T fp16 ----------------
__global__ __launch_bounds__(256) void pil_prep(const float* __restrict__ W2) {
    int t = blockIdx.x * 256 + threadIdx.x;   // 0..131071 ; t = k*512 + n
    int k = t >> 9, n = t & 511;
    g_w2t[n * 256 + k] = __float2half_rn(W2[t]);
}

// ---------------- main: gather + tanh + GEMM2 + basis einsum ----------------
__global__ __launch_bounds__(256, 2) void pil_main(const void* __restrict__ pi,
                                                   const void* __restrict__ pj,
                                                   const float* __restrict__ basis,
                                                   float* __restrict__ out) {
    extern __shared__ char smem[];
    unsigned sb = smem_u32(smem);
    int tid  = threadIdx.x;
    int w    = tid >> 5;
    int l    = tid & 31;
    long pairbase = (long)blockIdx.x * TILE_M;

    // -- start W2 chunk 0/1 copies immediately (overlap with gather) --
    {
        #pragma unroll
        for (int i = 0; i < 4; i++) {
            int v = tid + i * 256;                    // 0..1023
            int r = v >> 5, seg = (v & 31) * 16;
            CP16(sb + SM_B + r * PITCH + seg, (const char*)g_w2t + (long)r * 512 + seg);
        }
        CP_COMMIT();
        #pragma unroll
        for (int i = 0; i < 4; i++) {
            int v = tid + i * 256;
            int r = v >> 5, seg = (v & 31) * 16;
            CP16(sb + SM_B + SM_BUF + r * PITCH + seg,
                 (const char*)g_w2t + (long)(32 + r) * 512 + seg);
        }
        CP_COMMIT();
    }

    // -- index dtype sniff (int64 vs silently-int32) --
    bool is64;
    {
        const unsigned* wds = (const unsigned*)pi;
        unsigned acc = 0;
        #pragma unroll
        for (int u = 1; u < 32; u += 2) acc |= wds[u];
        is64 = (acc == 0);
    }

    // -- basis fragments for epilogue --
    int r0 = 16 * w + (l >> 2);
    int s  = l & 3;
    float2 basA = *(const float2*)(basis + (pairbase + r0) * 8 + 2 * s);
    float2 basB = *(const float2*)(basis + (pairbase + r0 + 8) * 8 + 2 * s);

    // -- phase 1: gather q rows, tanh.approx, fp16 -> SMEM A --
    {
        int row = tid >> 1, half = tid & 1;
        long p = pairbase + row;
        long ii, jj;
        if (is64) { ii = ((const long long*)pi)[p]; jj = ((const long long*)pj)[p]; }
        else      { ii = ((const int*)pi)[p];       jj = ((const int*)pj)[p]; }
        const float4* qi = (const float4*)(g_q + ii * 256 + half * 128);
        const float4* qj = (const float4*)(g_q + jj * 256 + half * 128);
        char* dst = smem + row * PITCH + half * 256;
        #pragma unroll 8
        for (int j = 0; j < 32; j++) {
            float4 a = qi[j], b = qj[j];
            float v0 = tanh_approx(a.x + b.x);
            float v1 = tanh_approx(a.y + b.y);
            float v2 = tanh_approx(a.z + b.z);
            float v3 = tanh_approx(a.w + b.w);
            __half h0 = __float2half_rn(v0), h1 = __float2half_rn(v1);
            __half h2 = __float2half_rn(v2), h3 = __float2half_rn(v3);
            uint2 hv;
            hv.x = (unsigned)__half_as_ushort(h0) | ((unsigned)__half_as_ushort(h1) << 16);
            hv.y = (unsigned)__half_as_ushort(h2) | ((unsigned)__half_as_ushort(h3) << 16);
            *(uint2*)(dst + SM_A + j * 8) = hv;
        }
    }

    // -- per-lane ldmatrix bases --
    unsigned rowA = 16 * w + (l & 7) + ((l >> 3) & 1) * 8;
    unsigned colA = (l >> 4) * 16;                          // bytes
    unsigned aBase = sb + SM_A + rowA * PITCH + colA;
    unsigned rowBl = (l & 7) + (l >> 4) * 8;
    unsigned colBl = ((l >> 3) & 1) * 16;
    unsigned bLane = rowBl * PITCH + colBl;

    // -- phase 2: 16 N-chunks of 32, double-buffered --
    for (int c = 0; c < 16; c++) {
        if (c < 15) CP_WAIT(1); else CP_WAIT(0);
        __syncthreads();                                    // chunk c resident, A ready

        unsigned bBase = sb + SM_B + (c & 1) * SM_BUF + bLane;
        float acc[4][4];
        #pragma unroll
        for (int n = 0; n < 4; n++)
            #pragma unroll
            for (int j = 0; j < 4; j++) acc[n][j] = 0.f;

        #pragma unroll
        for (int ks = 0; ks < 16; ks++) {
            unsigned ah[4], bb[4];
            ldmx4(ah, aBase + ks * 32);
            #pragma unroll
            for (int ntp = 0; ntp < 2; ntp++) {
                ldmx4(bb, bBase + ntp * (16 * PITCH) + ks * 32);
                mma16816(acc[2 * ntp],     ah, bb[0], bb[1]);
                mma16816(acc[2 * ntp + 1], ah, bb[2], bb[3]);
            }
        }
        __syncthreads();                                    // all reads of buf done
        if (c + 2 < 16) {                                   // refill buf (c&1) with chunk c+2
            unsigned dst = sb + SM_B + (c & 1) * SM_BUF;
            const char* src = (const char*)g_w2t + (long)(c + 2) * 32 * 512;
            #pragma unroll
            for (int i = 0; i < 4; i++) {
                int v = tid + i * 256;
                int r = v >> 5, seg = (v & 31) * 16;
                CP16(dst + r * PITCH + seg, src + (long)r * 512 + seg);
            }
            CP_COMMIT();
        }

        // epilogue: fold basis, reduce across the 4 lanes of each row-group, store
        #pragma unroll
        for (int nt = 0; nt < 4; nt++) {
            float v0 = acc[nt][0] * basA.x + acc[nt][1] * basA.y;
            float v1 = acc[nt][2] * basB.x + acc[nt][3] * basB.y;
            v0 += __shfl_xor_sync(0xFFFFFFFFu, v0, 1);
            v0 += __shfl_xor_sync(0xFFFFFFFFu, v0, 2);
            v1 += __shfl_xor_sync(0xFFFFFFFFu, v1, 1);
            v1 += __shfl_xor_sync(0xFFFFFFFFu, v1, 2);
            if ((l & 3) == 0) {
                int c_out = c * 4 + nt;
                out[(pairbase + r0) * 64 + c_out]     = v0;
                out[(pairbase + r0 + 8) * 64 + c_out] = v1;
            }
        }
    }
}

extern "C" void kernel_launch(void* const* d_in, const int* in_sizes, int n_in,
                              void* d_out, int out_size) {
    const float* p1    = (const float*)d_in[0];
    const void*  pi    = d_in[1];
    const void*  pj    = d_in[2];
    const float* basis = (const float*)d_in[3];
    const float* W1    = (const float*)d_in[4];
    const float* W2    = (const float*)d_in[5];
    (void)in_sizes; (void)n_in; (void)out_size;

    float* q;
    cudaGetSymbolAddress((void**)&q, g_q);

    cudaFuncSetAttribute(pil_main, cudaFuncAttributeMaxDynamicSharedMemorySize, SM_SIZE);

    pil_prep<<<512, 256>>>(W2);
    pil_q<<<dim3((N_NODES + 63) / 64, 4), 256>>>(p1, W1, q);
    pil_main<<<N_TILES, 256, SM_SIZE>>>(pi, pj, basis, (float*)d_out);
}

// round 9
// speedup vs baseline: 1.5054x; 1.2909x over previous
#include <cuda_runtime.h>
#include <cuda_fp16.h>

#define N_NODES   50000
#define N_PAIRS   800000
#define TILE_M    128
#define N_TILES   (N_PAIRS / TILE_M)       // 6250

// ---------------- main-kernel SMEM layout ----------------
#define PITCH     528                       // bytes per A row (256 halves + 8 pad)
#define SM_A      0                         // 128*528 = 67584 ; reused as out staging
#define SM_B      67584
#define BUF       8448                      // 16 rows * 528
#define NCHUNK    32                        // 32 chunks of 16 N-rows
#define OPITCH    68                        // out staging pitch in floats (272B, 16-aligned)
#define SM_SIZE   (67584 + 4 * BUF)         // 101376 -> occ 2

// ---------------- device scratch ----------------
__device__ __align__(16) float  g_q[(size_t)N_NODES * 256];   // p1 @ W1, fp32
__device__ __align__(16) __half g_w2t[512 * 256];             // W2^T as [n][k] fp16

// ---------------- helpers ----------------
__device__ __forceinline__ unsigned smem_u32(const void* p) {
    unsigned a;
    asm("{ .reg .u64 t; cvta.to.shared.u64 t, %1; cvt.u32.u64 %0, t; }" : "=r"(a) : "l"(p));
    return a;
}

__device__ __forceinline__ void ldmx4(unsigned* r, unsigned addr) {
    asm volatile("ldmatrix.sync.aligned.m8n8.x4.shared.b16 {%0,%1,%2,%3}, [%4];"
                 : "=r"(r[0]), "=r"(r[1]), "=r"(r[2]), "=r"(r[3]) : "r"(addr));
}

__device__ __forceinline__ void mma16816(float* c, const unsigned* a, unsigned b0, unsigned b1) {
    asm volatile("mma.sync.aligned.m16n8k16.row.col.f32.f16.f16.f32 "
                 "{%0,%1,%2,%3}, {%4,%5,%6,%7}, {%8,%9}, {%0,%1,%2,%3};"
                 : "+f"(c[0]), "+f"(c[1]), "+f"(c[2]), "+f"(c[3])
                 : "r"(a[0]), "r"(a[1]), "r"(a[2]), "r"(a[3]), "r"(b0), "r"(b1));
}

__device__ __forceinline__ float tanh_approx(float x) {
    float r;
    asm("tanh.approx.f32 %0, %1;" : "=f"(r) : "f"(x));
    return r;
}

#define CP16(sm, g)  asm volatile("cp.async.cg.shared.global [%0], [%1], 16;" :: "r"(sm), "l"(g) : "memory")
#define CP_COMMIT()  asm volatile("cp.async.commit_group;" ::: "memory")
#define CP_WAIT(n)   asm volatile("cp.async.wait_group %0;" :: "n"(n) : "memory")

// ---------------- kernel A: q = p1 @ W1 (fp32) ----------------
__global__ __launch_bounds__(256) void pil_q(const float* __restrict__ p1,
                                             const float* __restrict__ W1,
                                             float* __restrict__ q) {
    __shared__ float sA[64 * 68];
    __shared__ float sB[64 * 68];
    int tid = threadIdx.x;
    int m0 = blockIdx.x * 64, n0 = blockIdx.y * 64;

    #pragma unroll
    for (int i = 0; i < 4; i++) {
        int v = tid + i * 256;
        int r = v >> 4, c4 = (v & 15) * 4;
        float4 av = make_float4(0.f, 0.f, 0.f, 0.f);
        if (m0 + r < N_NODES) av = *(const float4*)(p1 + (long)(m0 + r) * 64 + c4);
        *(float4*)(sA + r * 68 + c4) = av;
        *(float4*)(sB + r * 68 + c4) = *(const float4*)(W1 + (long)r * 256 + n0 + c4);
    }
    __syncthreads();

    int tx = tid & 15, ty = tid >> 4;
    float c[4][4];
    #pragma unroll
    for (int i = 0; i < 4; i++)
        #pragma unroll
        for (int j = 0; j < 4; j++) c[i][j] = 0.f;

    #pragma unroll 8
    for (int k = 0; k < 64; k++) {
        float4 b = *(float4*)(sB + k * 68 + tx * 4);
        #pragma unroll
        for (int i = 0; i < 4; i++) {
            float a = sA[(ty * 4 + i) * 68 + k];
            c[i][0] = fmaf(a, b.x, c[i][0]);
            c[i][1] = fmaf(a, b.y, c[i][1]);
            c[i][2] = fmaf(a, b.z, c[i][2]);
            c[i][3] = fmaf(a, b.w, c[i][3]);
        }
    }
    #pragma unroll
    for (int i = 0; i < 4; i++) {
        int m = m0 + ty * 4 + i;
        if (m < N_NODES) {
            float4 o; o.x = c[i][0]; o.y = c[i][1]; o.z = c[i][2]; o.w = c[i][3];
            *(float4*)(q + (long)m * 256 + n0 + tx * 4) = o;
        }
    }
}

// ---------------- prep: W2^T fp16 ----------------
__global__ __launch_bounds__(256) void pil_prep(const float* __restrict__ W2) {
    int t = blockIdx.x * 256 + threadIdx.x;   // t = k*512 + n
    int k = t >> 9, n = t & 511;
    g_w2t[n * 256 + k] = __float2half_rn(W2[t]);
}

// ---------------- main: gather + tanh + GEMM2 + basis einsum ----------------
__global__ __launch_bounds__(256, 2) void pil_main(const void* __restrict__ pi,
                                                   const void* __restrict__ pj,
                                                   const float* __restrict__ basis,
                                                   float* __restrict__ out) {
    extern __shared__ char smem[];
    unsigned sb = smem_u32(smem);
    float* outS = (float*)smem;               // overlays A region (pitch OPITCH floats)
    int tid  = threadIdx.x;
    int w    = tid >> 5;
    int l    = tid & 31;
    long pairbase = (long)blockIdx.x * TILE_M;

    // -- prefetch W2 chunks 0..2 immediately (overlap with gather) --
    #pragma unroll
    for (int cc = 0; cc < 3; cc++) {
        #pragma unroll
        for (int i = 0; i < 2; i++) {
            int v = tid + i * 256;                    // 0..511
            int r = v >> 5, seg = (v & 31) * 16;
            CP16(sb + SM_B + cc * BUF + r * PITCH + seg,
                 (const char*)g_w2t + (long)(cc * 16 + r) * 512 + seg);
        }
        CP_COMMIT();
    }

    // -- index dtype sniff (int64 vs silently-int32) --
    bool is64;
    {
        const unsigned* wds = (const unsigned*)pi;
        unsigned acc = 0;
        #pragma unroll
        for (int u = 1; u < 32; u += 2) acc |= wds[u];
        is64 = (acc == 0);
    }

    // -- basis fragments for epilogue --
    int r0 = 16 * w + (l >> 2);
    int s  = l & 3;
    float2 basA = *(const float2*)(basis + (pairbase + r0) * 8 + 2 * s);
    float2 basB = *(const float2*)(basis + (pairbase + r0 + 8) * 8 + 2 * s);

    // -- phase 1: gather q rows, tanh.approx, fp16 -> SMEM A (warp-local rows) --
    {
        int row = tid >> 1, half = tid & 1;
        long p = pairbase + row;
        long ii, jj;
        if (is64) { ii = ((const long long*)pi)[p]; jj = ((const long long*)pj)[p]; }
        else      { ii = ((const int*)pi)[p];       jj = ((const int*)pj)[p]; }
        const float4* qi = (const float4*)(g_q + ii * 256 + half * 128);
        const float4* qj = (const float4*)(g_q + jj * 256 + half * 128);
        char* dst = smem + row * PITCH + half * 256;
        #pragma unroll 8
        for (int j = 0; j < 32; j++) {
            float4 a = qi[j], b = qj[j];
            float v0 = tanh_approx(a.x + b.x);
            float v1 = tanh_approx(a.y + b.y);
            float v2 = tanh_approx(a.z + b.z);
            float v3 = tanh_approx(a.w + b.w);
            __half h0 = __float2half_rn(v0), h1 = __float2half_rn(v1);
            __half h2 = __float2half_rn(v2), h3 = __float2half_rn(v3);
            uint2 hv;
            hv.x = (unsigned)__half_as_ushort(h0) | ((unsigned)__half_as_ushort(h1) << 16);
            hv.y = (unsigned)__half_as_ushort(h2) | ((unsigned)__half_as_ushort(h3) << 16);
            *(uint2*)(dst + j * 8) = hv;
        }
    }
    __syncwarp();   // A rows for this warp are warp-local: warp-level sync suffices

    // -- load A fragments into registers once (64 regs/thread) --
    unsigned a[16][4];
    {
        unsigned rowA = 16 * w + (l & 7) + ((l >> 3) & 1) * 8;
        unsigned colA = (l >> 4) * 16;
        unsigned aBase = sb + rowA * PITCH + colA;
        #pragma unroll
        for (int ks = 0; ks < 16; ks++) ldmx4(a[ks], aBase + ks * 32);
    }

    // -- per-lane B ldmatrix base --
    unsigned rowBl = (l & 7) + (l >> 4) * 8;
    unsigned colBl = ((l >> 3) & 1) * 16;
    unsigned bLane = rowBl * PITCH + colBl;

    // -- phase 2: 32 N-chunks of 16, 4-deep cp.async pipeline, 1 barrier/chunk --
    for (int c = 0; c < NCHUNK; c++) {
        if (c < NCHUNK - 2)      CP_WAIT(2);
        else if (c == NCHUNK - 2) CP_WAIT(1);
        else                      CP_WAIT(0);
        __syncthreads();          // chunk c resident; buffer (c+3)&3 free; A frags loaded

        if (c + 3 < NCHUNK) {     // prefetch chunk c+3
            unsigned dst = sb + SM_B + ((c + 3) & 3) * BUF;
            const char* src = (const char*)g_w2t + (long)(c + 3) * 16 * 512;
            #pragma unroll
            for (int i = 0; i < 2; i++) {
                int v = tid + i * 256;
                int r = v >> 5, seg = (v & 31) * 16;
                CP16(dst + r * PITCH + seg, src + (long)r * 512 + seg);
            }
            CP_COMMIT();
        }

        unsigned bBase = sb + SM_B + (c & 3) * BUF + bLane;
        float acc[2][4];
        #pragma unroll
        for (int n = 0; n < 2; n++)
            #pragma unroll
            for (int j = 0; j < 4; j++) acc[n][j] = 0.f;

        #pragma unroll
        for (int ks = 0; ks < 16; ks++) {
            unsigned bb[4];
            ldmx4(bb, bBase + ks * 32);
            mma16816(acc[0], a[ks], bb[0], bb[1]);
            mma16816(acc[1], a[ks], bb[2], bb[3]);
        }

        // epilogue: fold basis, reduce lane quads, stage into outS (A region, now dead)
        #pragma unroll
        for (int nt = 0; nt < 2; nt++) {
            float v0 = acc[nt][0] * basA.x + acc[nt][1] * basA.y;
            float v1 = acc[nt][2] * basB.x + acc[nt][3] * basB.y;
            v0 += __shfl_xor_sync(0xFFFFFFFFu, v0, 1);
            v0 += __shfl_xor_sync(0xFFFFFFFFu, v0, 2);
            v1 += __shfl_xor_sync(0xFFFFFFFFu, v1, 1);
            v1 += __shfl_xor_sync(0xFFFFFFFFu, v1, 2);
            if ((l & 3) == 0) {
                int c_out = c * 2 + nt;
                outS[r0 * OPITCH + c_out]       = v0;
                outS[(r0 + 8) * OPITCH + c_out] = v1;
            }
        }
    }

    // -- final coalesced store: outS[128][64] -> out --
    __syncthreads();
    #pragma unroll
    for (int i = 0; i < 8; i++) {
        int idx = tid + i * 256;              // 0..2047
        int r = idx >> 4, c4 = (idx & 15) * 4;
        float4 v = *(float4*)(outS + r * OPITCH + c4);
        *(float4*)(out + (pairbase + r) * 64 + c4) = v;
    }
}

extern "C" void kernel_launch(void* const* d_in, const int* in_sizes, int n_in,
                              void* d_out, int out_size) {
    const float* p1    = (const float*)d_in[0];
    const void*  pi    = d_in[1];
    const void*  pj    = d_in[2];
    const float* basis = (const float*)d_in[3];
    const float* W1    = (const float*)d_in[4];
    const float* W2    = (const float*)d_in[5];
    (void)in_sizes; (void)n_in; (void)out_size;

    float* q;
    cudaGetSymbolAddress((void**)&q, g_q);

    cudaFuncSetAttribute(pil_main, cudaFuncAttributeMaxDynamicSharedMemorySize, SM_SIZE);

    pil_prep<<<512, 256>>>(W2);
    pil_q<<<dim3((N_NODES + 63) / 64, 4), 256>>>(p1, W1, q);
    pil_main<<<N_TILES, 256, SM_SIZE>>>(pi, pj, basis, (float*)d_out);
}

// round 10
// speedup vs baseline: 2.0283x; 1.3473x over previous
#include <cuda_runtime.h>
#include <cuda_fp16.h>

#define N_NODES   50000
#define N_PAIRS   800000
#define TILE_M    128
#define N_TILES   (N_PAIRS / TILE_M)       // 6250

// ---------------- main-kernel SMEM layout ----------------
#define PITCH     528                       // bytes per A row (256 halves + 8 pad)
#define SM_A      0                         // 128*528 = 67584 ; reused as out staging
#define SM_B      67584
#define BUF       8448                      // 16 rows * 528
#define NGROUP    16                        // 16 groups of 2 chunks (32 N-rows each)
#define OPITCH    68                        // out staging pitch in floats (272B, 16-aligned)
#define SM_SIZE   (67584 + 4 * BUF)         // 101376 -> occ 2

// ---------------- device scratch ----------------
__device__ __align__(16) __half g_q[(size_t)N_NODES * 256];   // p1 @ W1, fp16
__device__ __align__(16) __half g_w2t[512 * 256];             // W2^T as [n][k] fp16

// ---------------- helpers ----------------
__device__ __forceinline__ unsigned smem_u32(const void* p) {
    unsigned a;
    asm("{ .reg .u64 t; cvta.to.shared.u64 t, %1; cvt.u32.u64 %0, t; }" : "=r"(a) : "l"(p));
    return a;
}

__device__ __forceinline__ void ldmx4(unsigned* r, unsigned addr) {
    asm volatile("ldmatrix.sync.aligned.m8n8.x4.shared.b16 {%0,%1,%2,%3}, [%4];"
                 : "=r"(r[0]), "=r"(r[1]), "=r"(r[2]), "=r"(r[3]) : "r"(addr));
}

__device__ __forceinline__ void mma16816(float* c, const unsigned* a, unsigned b0, unsigned b1) {
    asm volatile("mma.sync.aligned.m16n8k16.row.col.f32.f16.f16.f32 "
                 "{%0,%1,%2,%3}, {%4,%5,%6,%7}, {%8,%9}, {%0,%1,%2,%3};"
                 : "+f"(c[0]), "+f"(c[1]), "+f"(c[2]), "+f"(c[3])
                 : "r"(a[0]), "r"(a[1]), "r"(a[2]), "r"(a[3]), "r"(b0), "r"(b1));
}

__device__ __forceinline__ float tanh_approx(float x) {
    float r;
    asm("tanh.approx.f32 %0, %1;" : "=f"(r) : "f"(x));
    return r;
}

#define CP16(sm, g)  asm volatile("cp.async.cg.shared.global [%0], [%1], 16;" :: "r"(sm), "l"(g) : "memory")
#define CP_COMMIT()  asm volatile("cp.async.commit_group;" ::: "memory")
#define CP_WAIT0()   asm volatile("cp.async.wait_group 0;" ::: "memory")

// ---------------- kernel A: q = p1 @ W1 (fp32 math, fp16 store) ----------------
__global__ __launch_bounds__(256) void pil_q(const float* __restrict__ p1,
                                             const float* __restrict__ W1,
                                             __half* __restrict__ q) {
    __shared__ float sA[64 * 68];
    __shared__ float sB[64 * 68];
    int tid = threadIdx.x;
    int m0 = blockIdx.x * 64, n0 = blockIdx.y * 64;

    #pragma unroll
    for (int i = 0; i < 4; i++) {
        int v = tid + i * 256;
        int r = v >> 4, c4 = (v & 15) * 4;
        float4 av = make_float4(0.f, 0.f, 0.f, 0.f);
        if (m0 + r < N_NODES) av = *(const float4*)(p1 + (long)(m0 + r) * 64 + c4);
        *(float4*)(sA + r * 68 + c4) = av;
        *(float4*)(sB + r * 68 + c4) = *(const float4*)(W1 + (long)r * 256 + n0 + c4);
    }
    __syncthreads();

    int tx = tid & 15, ty = tid >> 4;
    float c[4][4];
    #pragma unroll
    for (int i = 0; i < 4; i++)
        #pragma unroll
        for (int j = 0; j < 4; j++) c[i][j] = 0.f;

    #pragma unroll 8
    for (int k = 0; k < 64; k++) {
        float4 b = *(float4*)(sB + k * 68 + tx * 4);
        #pragma unroll
        for (int i = 0; i < 4; i++) {
            float a = sA[(ty * 4 + i) * 68 + k];
            c[i][0] = fmaf(a, b.x, c[i][0]);
            c[i][1] = fmaf(a, b.y, c[i][1]);
            c[i][2] = fmaf(a, b.z, c[i][2]);
            c[i][3] = fmaf(a, b.w, c[i][3]);
        }
    }
    #pragma unroll
    for (int i = 0; i < 4; i++) {
        int m = m0 + ty * 4 + i;
        if (m < N_NODES) {
            __half2 h01 = __floats2half2_rn(c[i][0], c[i][1]);
            __half2 h23 = __floats2half2_rn(c[i][2], c[i][3]);
            uint2 o;
            o.x = *(unsigned*)&h01;
            o.y = *(unsigned*)&h23;
            *(uint2*)(q + (long)m * 256 + n0 + tx * 4) = o;
        }
    }
}

// ---------------- prep: W2^T fp16 ----------------
__global__ __launch_bounds__(256) void pil_prep(const float* __restrict__ W2) {
    int t = blockIdx.x * 256 + threadIdx.x;   // t = k*512 + n
    int k = t >> 9, n = t & 511;
    g_w2t[n * 256 + k] = __float2half_rn(W2[t]);
}

// ---------------- main: gather + tanh + GEMM2 + basis einsum ----------------
__global__ __launch_bounds__(256, 2) void pil_main(const void* __restrict__ pi,
                                                   const void* __restrict__ pj,
                                                   const float* __restrict__ basis,
                                                   float* __restrict__ out) {
    extern __shared__ char smem[];
    unsigned sb = smem_u32(smem);
    float* outS = (float*)smem;               // overlays A region (pitch OPITCH floats)
    int tid  = threadIdx.x;
    int w    = tid >> 5;
    int l    = tid & 31;
    long pairbase = (long)blockIdx.x * TILE_M;

    // -- prefetch W2 group 0 (chunks 0,1 = rows 0..31) immediately --
    {
        #pragma unroll
        for (int i = 0; i < 4; i++) {
            int v = tid + i * 256;                    // 0..1023
            int r = v >> 5, seg = (v & 31) * 16;
            CP16(sb + SM_B + r * PITCH + seg, (const char*)g_w2t + (long)r * 512 + seg);
        }
        CP_COMMIT();
    }

    // -- index dtype sniff (int64 vs silently-int32) --
    bool is64;
    {
        const unsigned* wds = (const unsigned*)pi;
        unsigned acc = 0;
        #pragma unroll
        for (int u = 1; u < 32; u += 2) acc |= wds[u];
        is64 = (acc == 0);
    }

    // -- basis fragments for epilogue --
    int r0 = 16 * w + (l >> 2);
    int s  = l & 3;
    float2 basA = *(const float2*)(basis + (pairbase + r0) * 8 + 2 * s);
    float2 basB = *(const float2*)(basis + (pairbase + r0 + 8) * 8 + 2 * s);

    // -- phase 1: gather q rows (fp16), tanh.approx -> SMEM A (warp-local rows) --
    {
        int row = tid >> 1, half = tid & 1;
        long p = pairbase + row;
        long ii, jj;
        if (is64) { ii = ((const long long*)pi)[p]; jj = ((const long long*)pj)[p]; }
        else      { ii = ((const int*)pi)[p];       jj = ((const int*)pj)[p]; }
        const uint4* qi = (const uint4*)(g_q + (size_t)ii * 256 + half * 128);
        const uint4* qj = (const uint4*)(g_q + (size_t)jj * 256 + half * 128);
        char* dst = smem + row * PITCH + half * 256;
        #pragma unroll 4
        for (int j = 0; j < 16; j++) {
            uint4 A = qi[j], B = qj[j];
            uint4 O;
            {
                float2 fa = __half22float2(*(__half2*)&A.x), fb = __half22float2(*(__half2*)&B.x);
                __half2 h = __floats2half2_rn(tanh_approx(fa.x + fb.x), tanh_approx(fa.y + fb.y));
                O.x = *(unsigned*)&h;
            }
            {
                float2 fa = __half22float2(*(__half2*)&A.y), fb = __half22float2(*(__half2*)&B.y);
                __half2 h = __floats2half2_rn(tanh_approx(fa.x + fb.x), tanh_approx(fa.y + fb.y));
                O.y = *(unsigned*)&h;
            }
            {
                float2 fa = __half22float2(*(__half2*)&A.z), fb = __half22float2(*(__half2*)&B.z);
                __half2 h = __floats2half2_rn(tanh_approx(fa.x + fb.x), tanh_approx(fa.y + fb.y));
                O.z = *(unsigned*)&h;
            }
            {
                float2 fa = __half22float2(*(__half2*)&A.w), fb = __half22float2(*(__half2*)&B.w);
                __half2 h = __floats2half2_rn(tanh_approx(fa.x + fb.x), tanh_approx(fa.y + fb.y));
                O.w = *(unsigned*)&h;
            }
            *(uint4*)(dst + j * 16) = O;
        }
    }
    __syncwarp();   // A rows for this warp are warp-local: warp-level sync suffices

    // -- load A fragments into registers once (64 regs/thread) --
    unsigned a[16][4];
    {
        unsigned rowA = 16 * w + (l & 7) + ((l >> 3) & 1) * 8;
        unsigned colA = (l >> 4) * 16;
        unsigned aBase = sb + rowA * PITCH + colA;
        #pragma unroll
        for (int ks = 0; ks < 16; ks++) ldmx4(a[ks], aBase + ks * 32);
    }

    // -- per-lane B ldmatrix base --
    unsigned rowBl = (l & 7) + (l >> 4) * 8;
    unsigned colBl = ((l >> 3) & 1) * 16;
    unsigned bLane = rowBl * PITCH + colBl;

    // -- phase 2: 16 groups of 2 chunks (32 N-rows), distance-1 double buffer --
    for (int it = 0; it < NGROUP; it++) {
        CP_WAIT0();               // group it resident
        __syncthreads();          // ... and pair (it+1)&1 free (prev group's reads done)

        if (it + 1 < NGROUP) {    // prefetch group it+1 into the other buffer pair
            unsigned dst = sb + SM_B + ((it + 1) & 1) * (2 * BUF);
            const char* src = (const char*)g_w2t + (long)(it + 1) * 32 * 512;
            #pragma unroll
            for (int i = 0; i < 4; i++) {
                int v = tid + i * 256;                // 0..1023
                int r = v >> 5, seg = (v & 31) * 16;
                CP16(dst + r * PITCH + seg, src + (long)r * 512 + seg);
            }
            CP_COMMIT();
        }

        unsigned bBase0 = sb + SM_B + (it & 1) * (2 * BUF) + bLane;
        unsigned bBase1 = bBase0 + BUF;
        float acc[4][4];
        #pragma unroll
        for (int n = 0; n < 4; n++)
            #pragma unroll
            for (int j = 0; j < 4; j++) acc[n][j] = 0.f;

        #pragma unroll
        for (int ks = 0; ks < 16; ks++) {
            unsigned b0[4], b1[4];
            ldmx4(b0, bBase0 + ks * 32);
            ldmx4(b1, bBase1 + ks * 32);
            mma16816(acc[0], a[ks], b0[0], b0[1]);
            mma16816(acc[1], a[ks], b0[2], b0[3]);
            mma16816(acc[2], a[ks], b1[0], b1[1]);
            mma16816(acc[3], a[ks], b1[2], b1[3]);
        }

        // epilogue: fold basis, reduce lane quads, stage into outS (A region, now dead)
        #pragma unroll
        for (int nt = 0; nt < 4; nt++) {
            float v0 = acc[nt][0] * basA.x + acc[nt][1] * basA.y;
            float v1 = acc[nt][2] * basB.x + acc[nt][3] * basB.y;
            v0 += __shfl_xor_sync(0xFFFFFFFFu, v0, 1);
            v0 += __shfl_xor_sync(0xFFFFFFFFu, v0, 2);
            v1 += __shfl_xor_sync(0xFFFFFFFFu, v1, 1);
            v1 += __shfl_xor_sync(0xFFFFFFFFu, v1, 2);
            if ((l & 3) == 0) {
                int c_out = it * 4 + nt;
                outS[r0 * OPITCH + c_out]       = v0;
                outS[(r0 + 8) * OPITCH + c_out] = v1;
            }
        }
    }

    // -- final coalesced store: outS[128][64] -> out --
    __syncthreads();
    #pragma unroll
    for (int i = 0; i < 8; i++) {
        int idx = tid + i * 256;              // 0..2047
        int r = idx >> 4, c4 = (idx & 15) * 4;
        float4 v = *(float4*)(outS + r * OPITCH + c4);
        *(float4*)(out + (pairbase + r) * 64 + c4) = v;
    }
}

extern "C" void kernel_launch(void* const* d_in, const int* in_sizes, int n_in,
                              void* d_out, int out_size) {
    const float* p1    = (const float*)d_in[0];
    const void*  pi    = d_in[1];
    const void*  pj    = d_in[2];
    const float* basis = (const float*)d_in[3];
    const float* W1    = (const float*)d_in[4];
    const float* W2    = (const float*)d_in[5];
    (void)in_sizes; (void)n_in; (void)out_size;

    __half* q;
    cudaGetSymbolAddress((void**)&q, g_q);

    cudaFuncSetAttribute(pil_main, cudaFuncAttributeMaxDynamicSharedMemorySize, SM_SIZE);

    pil_prep<<<512, 256>>>(W2);
    pil_q<<<dim3((N_NODES + 63) / 64, 4), 256>>>(p1, W1, q);
    pil_main<<<N_TILES, 256, SM_SIZE>>>(pi, pj, basis, (float*)d_out);
}

// round 12
// speedup vs baseline: 2.1102x; 1.0404x over previous
#include <cuda_runtime.h>
#include <cuda_fp16.h>

#define N_NODES   50000
#define N_PAIRS   800000
#define TILE_M    128
#define N_TILES   (N_PAIRS / TILE_M)       // 6250

// ---------------- main-kernel SMEM layout ----------------
#define PITCH     528                       // bytes per A row (256 halves + 8 pad)
#define SM_A      0                         // 128*528 = 67584 ; reused as out staging
#define SM_B      67584
#define BUF       8448                      // 16 rows * 528
#define NGROUP    16                        // 16 groups of 2 chunks (32 N-rows each)
#define OPITCH    68                        // out staging pitch in floats (272B, 16-aligned)
#define SM_SIZE   (67584 + 4 * BUF)         // 101376 -> occ 2

// ---------------- device scratch ----------------
__device__ __align__(16) __half g_q[(size_t)N_NODES * 256];   // p1 @ W1, fp16
__device__ __align__(16) __half g_w2t[512 * 256];             // W2^T as [n][k] fp16

// ---------------- helpers ----------------
__device__ __forceinline__ unsigned smem_u32(const void* p) {
    unsigned a;
    asm("{ .reg .u64 t; cvta.to.shared.u64 t, %1; cvt.u32.u64 %0, t; }" : "=r"(a) : "l"(p));
    return a;
}

__device__ __forceinline__ void ldmx4(unsigned* r, unsigned addr) {
    asm volatile("ldmatrix.sync.aligned.m8n8.x4.shared.b16 {%0,%1,%2,%3}, [%4];"
                 : "=r"(r[0]), "=r"(r[1]), "=r"(r[2]), "=r"(r[3]) : "r"(addr));
}

__device__ __forceinline__ void mma16816(float* c, const unsigned* a, unsigned b0, unsigned b1) {
    asm volatile("mma.sync.aligned.m16n8k16.row.col.f32.f16.f16.f32 "
                 "{%0,%1,%2,%3}, {%4,%5,%6,%7}, {%8,%9}, {%0,%1,%2,%3};"
                 : "+f"(c[0]), "+f"(c[1]), "+f"(c[2]), "+f"(c[3])
                 : "r"(a[0]), "r"(a[1]), "r"(a[2]), "r"(a[3]), "r"(b0), "r"(b1));
}

__device__ __forceinline__ float tanh_approx(float x) {
    float r;
    asm("tanh.approx.f32 %0, %1;" : "=f"(r) : "f"(x));
    return r;
}

#define CP16(sm, g)  asm volatile("cp.async.cg.shared.global [%0], [%1], 16;" :: "r"(sm), "l"(g) : "memory")
#define CP_COMMIT()  asm volatile("cp.async.commit_group;" ::: "memory")
#define CP_WAIT0()   asm volatile("cp.async.wait_group 0;" ::: "memory")

// ---------------- kernel A: q = p1 @ W1 (fp32 math, fp16 store) ----------------
__global__ __launch_bounds__(256) void pil_q(const float* __restrict__ p1,
                                             const float* __restrict__ W1,
                                             __half* __restrict__ q) {
    __shared__ float sA[64 * 68];
    __shared__ float sB[64 * 68];
    int tid = threadIdx.x;
    int m0 = blockIdx.x * 64, n0 = blockIdx.y * 64;

    #pragma unroll
    for (int i = 0; i < 4; i++) {
        int v = tid + i * 256;
        int r = v >> 4, c4 = (v & 15) * 4;
        float4 av = make_float4(0.f, 0.f, 0.f, 0.f);
        if (m0 + r < N_NODES) av = *(const float4*)(p1 + (long)(m0 + r) * 64 + c4);
        *(float4*)(sA + r * 68 + c4) = av;
        *(float4*)(sB + r * 68 + c4) = *(const float4*)(W1 + (long)r * 256 + n0 + c4);
    }
    __syncthreads();

    int tx = tid & 15, ty = tid >> 4;
    float c[4][4];
    #pragma unroll
    for (int i = 0; i < 4; i++)
        #pragma unroll
        for (int j = 0; j < 4; j++) c[i][j] = 0.f;

    #pragma unroll 8
    for (int k = 0; k < 64; k++) {
        float4 b = *(float4*)(sB + k * 68 + tx * 4);
        #pragma unroll
        for (int i = 0; i < 4; i++) {
            float a = sA[(ty * 4 + i) * 68 + k];
            c[i][0] = fmaf(a, b.x, c[i][0]);
            c[i][1] = fmaf(a, b.y, c[i][1]);
            c[i][2] = fmaf(a, b.z, c[i][2]);
            c[i][3] = fmaf(a, b.w, c[i][3]);
        }
    }
    #pragma unroll
    for (int i = 0; i < 4; i++) {
        int m = m0 + ty * 4 + i;
        if (m < N_NODES) {
            __half2 h01 = __floats2half2_rn(c[i][0], c[i][1]);
            __half2 h23 = __floats2half2_rn(c[i][2], c[i][3]);
            uint2 o;
            o.x = *(unsigned*)&h01;
            o.y = *(unsigned*)&h23;
            *(uint2*)(q + (long)m * 256 + n0 + tx * 4) = o;
        }
    }
}

// ---------------- prep: W2^T fp16 ----------------
__global__ __launch_bounds__(256) void pil_prep(const float* __restrict__ W2) {
    int t = blockIdx.x * 256 + threadIdx.x;   // t = k*512 + n
    int k = t >> 9, n = t & 511;
    g_w2t[n * 256 + k] = __float2half_rn(W2[t]);
}

// ---------------- main: gather + tanh + GEMM2 + basis einsum ----------------
// 128 threads / 4 warps; each warp owns 32 pair-rows (2 m16 tiles).
__global__ __launch_bounds__(128, 2) void pil_main(const void* __restrict__ pi,
                                                   const void* __restrict__ pj,
                                                   const float* __restrict__ basis,
                                                   float* __restrict__ out) {
    extern __shared__ char smem[];
    unsigned sb = smem_u32(smem);
    float* outS = (float*)smem;               // overlays A region (pitch OPITCH floats)
    int tid  = threadIdx.x;
    int w    = tid >> 5;
    int l    = tid & 31;
    long pairbase = (long)blockIdx.x * TILE_M;

    // -- prefetch W2 group 0 (rows 0..31) immediately --
    {
        #pragma unroll
        for (int i = 0; i < 8; i++) {
            int v = tid + i * 128;                    // 0..1023
            int r = v >> 5, seg = (v & 31) * 16;
            CP16(sb + SM_B + r * PITCH + seg, (const char*)g_w2t + (long)r * 512 + seg);
        }
        CP_COMMIT();
    }

    // -- index dtype sniff (int64 vs silently-int32) --
    bool is64;
    {
        const unsigned* wds = (const unsigned*)pi;
        unsigned acc = 0;
        #pragma unroll
        for (int u = 1; u < 32; u += 2) acc |= wds[u];
        is64 = (acc == 0);
    }

    // -- basis fragments for epilogue: 4 rows per lane (2 m-tiles x 2 row-halves) --
    int r0 = 32 * w + (l >> 2);                 // m-tile 0, first half
    int s  = l & 3;
    float2 basA0 = *(const float2*)(basis + (pairbase + r0) * 8 + 2 * s);
    float2 basB0 = *(const float2*)(basis + (pairbase + r0 + 8) * 8 + 2 * s);
    float2 basA1 = *(const float2*)(basis + (pairbase + r0 + 16) * 8 + 2 * s);
    float2 basB1 = *(const float2*)(basis + (pairbase + r0 + 24) * 8 + 2 * s);

    // -- phase 1: gather q row (fp16), tanh.approx -> SMEM A (1 row / thread) --
    {
        int row = tid;
        long p = pairbase + row;
        long ii, jj;
        if (is64) { ii = ((const long long*)pi)[p]; jj = ((const long long*)pj)[p]; }
        else      { ii = ((const int*)pi)[p];       jj = ((const int*)pj)[p]; }
        const uint4* qi = (const uint4*)(g_q + (size_t)ii * 256);
        const uint4* qj = (const uint4*)(g_q + (size_t)jj * 256);
        char* dst = smem + row * PITCH;
        #pragma unroll 4
        for (int j = 0; j < 32; j++) {
            uint4 A = qi[j], B = qj[j];
            uint4 O;
            {
                float2 fa = __half22float2(*(__half2*)&A.x), fb = __half22float2(*(__half2*)&B.x);
                __half2 h = __floats2half2_rn(tanh_approx(fa.x + fb.x), tanh_approx(fa.y + fb.y));
                O.x = *(unsigned*)&h;
            }
            {
                float2 fa = __half22float2(*(__half2*)&A.y), fb = __half22float2(*(__half2*)&B.y);
                __half2 h = __floats2half2_rn(tanh_approx(fa.x + fb.x), tanh_approx(fa.y + fb.y));
                O.y = *(unsigned*)&h;
            }
            {
                float2 fa = __half22float2(*(__half2*)&A.z), fb = __half22float2(*(__half2*)&B.z);
                __half2 h = __floats2half2_rn(tanh_approx(fa.x + fb.x), tanh_approx(fa.y + fb.y));
                O.z = *(unsigned*)&h;
            }
            {
                float2 fa = __half22float2(*(__half2*)&A.w), fb = __half22float2(*(__half2*)&B.w);
                __half2 h = __floats2half2_rn(tanh_approx(fa.x + fb.x), tanh_approx(fa.y + fb.y));
                O.w = *(unsigned*)&h;
            }
            *(uint4*)(dst + j * 16) = O;
        }
    }
    __syncwarp();   // warp w wrote rows 32w..32w+31 == exactly its own A rows

    // -- load A fragments for both m-tiles into registers (128 regs/thread) --
    unsigned a0[16][4], a1[16][4];
    {
        unsigned rowA = 32 * w + (l & 7) + ((l >> 3) & 1) * 8;
        unsigned colA = (l >> 4) * 16;
        unsigned aBase = sb + rowA * PITCH + colA;
        #pragma unroll
        for (int ks = 0; ks < 16; ks++) ldmx4(a0[ks], aBase + ks * 32);
        #pragma unroll
        for (int ks = 0; ks < 16; ks++) ldmx4(a1[ks], aBase + 16 * PITCH + ks * 32);
    }

    // -- per-lane B ldmatrix base --
    unsigned rowBl = (l & 7) + (l >> 4) * 8;
    unsigned colBl = ((l >> 3) & 1) * 16;
    unsigned bLane = rowBl * PITCH + colBl;

    // -- phase 2: 16 groups of 2 chunks (32 N-rows), distance-1 double buffer --
    for (int it = 0; it < NGROUP; it++) {
        CP_WAIT0();               // group it resident
        __syncthreads();          // ... and other buffer pair free

        if (it + 1 < NGROUP) {    // prefetch group it+1 into the other buffer pair
            unsigned dst = sb + SM_B + ((it + 1) & 1) * (2 * BUF);
            const char* src = (const char*)g_w2t + (long)(it + 1) * 32 * 512;
            #pragma unroll
            for (int i = 0; i < 8; i++) {
                int v = tid + i * 128;                // 0..1023
                int r = v >> 5, seg = (v & 31) * 16;
                CP16(dst + r * PITCH + seg, src + (long)r * 512 + seg);
            }
            CP_COMMIT();
        }

        unsigned bBase0 = sb + SM_B + (it & 1) * (2 * BUF) + bLane;
        unsigned bBase1 = bBase0 + BUF;
        float acc0[4][4], acc1[4][4];                 // [n-tile][frag], per m-tile
        #pragma unroll
        for (int n = 0; n < 4; n++)
            #pragma unroll
            for (int j = 0; j < 4; j++) { acc0[n][j] = 0.f; acc1[n][j] = 0.f; }

        #pragma unroll
        for (int ks = 0; ks < 16; ks++) {
            unsigned b0[4], b1[4];
            ldmx4(b0, bBase0 + ks * 32);
            ldmx4(b1, bBase1 + ks * 32);
            mma16816(acc0[0], a0[ks], b0[0], b0[1]);
            mma16816(acc0[1], a0[ks], b0[2], b0[3]);
            mma16816(acc0[2], a0[ks], b1[0], b1[1]);
            mma16816(acc0[3], a0[ks], b1[2], b1[3]);
            mma16816(acc1[0], a1[ks], b0[0], b0[1]);
            mma16816(acc1[1], a1[ks], b0[2], b0[3]);
            mma16816(acc1[2], a1[ks], b1[0], b1[1]);
            mma16816(acc1[3], a1[ks], b1[2], b1[3]);
        }

        // epilogue: fold basis, reduce lane quads, stage into outS (A region, now dead)
        #pragma unroll
        for (int nt = 0; nt < 4; nt++) {
            float u0 = acc0[nt][0] * basA0.x + acc0[nt][1] * basA0.y;
            float u1 = acc0[nt][2] * basB0.x + acc0[nt][3] * basB0.y;
            float u2 = acc1[nt][0] * basA1.x + acc1[nt][1] * basA1.y;
            float u3 = acc1[nt][2] * basB1.x + acc1[nt][3] * basB1.y;
            u0 += __shfl_xor_sync(0xFFFFFFFFu, u0, 1);
            u1 += __shfl_xor_sync(0xFFFFFFFFu, u1, 1);
            u2 += __shfl_xor_sync(0xFFFFFFFFu, u2, 1);
            u3 += __shfl_xor_sync(0xFFFFFFFFu, u3, 1);
            u0 += __shfl_xor_sync(0xFFFFFFFFu, u0, 2);
            u1 += __shfl_xor_sync(0xFFFFFFFFu, u1, 2);
            u2 += __shfl_xor_sync(0xFFFFFFFFu, u2, 2);
            u3 += __shfl_xor_sync(0xFFFFFFFFu, u3, 2);
            if ((l & 3) == 0) {
                int c_out = it * 4 + nt;
                outS[r0 * OPITCH + c_out]        = u0;
                outS[(r0 + 8) * OPITCH + c_out]  = u1;
                outS[(r0 + 16) * OPITCH + c_out] = u2;
                outS[(r0 + 24) * OPITCH + c_out] = u3;
            }
        }
    }

    // -- final coalesced store: outS[128][64] -> out --
    __syncthreads();
    #pragma unroll
    for (int i = 0; i < 16; i++) {
        int idx = tid + i * 128;              // 0..2047
        int r = idx >> 4, c4 = (idx & 15) * 4;
        float4 v = *(float4*)(outS + r * OPITCH + c4);
        *(float4*)(out + (pairbase + r) * 64 + c4) = v;
    }
}

extern "C" void kernel_launch(void* const* d_in, const int* in_sizes, int n_in,
                              void* d_out, int out_size) {
    const float* p1    = (const float*)d_in[0];
    const void*  pi    = d_in[1];
    const void*  pj    = d_in[2];
    const float* basis = (const float*)d_in[3];
    const float* W1    = (const float*)d_in[4];
    const float* W2    = (const float*)d_in[5];
    (void)in_sizes; (void)n_in; (void)out_size;

    __half* q;
    cudaGetSymbolAddress((void**)&q, g_q);

    cudaFuncSetAttribute(pil_main, cudaFuncAttributeMaxDynamicSharedMemorySize, SM_SIZE);

    pil_prep<<<512, 256>>>(W2);
    pil_q<<<dim3((N_NODES + 63) / 64, 4), 256>>>(p1, W1, q);
    pil_main<<<N_TILES, 128, SM_SIZE>>>(pi, pj, basis, (float*)d_out);
}